// round 4
// baseline (speedup 1.0000x reference)
#include <cuda_runtime.h>
#include <cuda_bf16.h>

#define B_    16
#define T_    2048
#define NTOK  (B_*T_)

typedef unsigned long long u64;

__device__ __forceinline__ u64 pack2(float lo, float hi){
    u64 r; asm("mov.b64 %0,{%1,%2};" : "=l"(r) : "f"(lo), "f"(hi)); return r;
}
__device__ __forceinline__ void unpack2(u64 v, float& lo, float& hi){
    asm("mov.b64 {%0,%1},%2;" : "=f"(lo), "=f"(hi) : "l"(v));
}
__device__ __forceinline__ u64 fma2(u64 a, u64 b, u64 c){
    u64 d; asm("fma.rn.f32x2 %0,%1,%2,%3;" : "=l"(d) : "l"(a), "l"(b), "l"(c)); return d;
}
__device__ __forceinline__ u64 mul2(u64 a, u64 b){
    u64 d; asm("mul.rn.f32x2 %0,%1,%2;" : "=l"(d) : "l"(a), "l"(b)); return d;
}
__device__ __forceinline__ u64 add2(u64 a, u64 b){
    u64 d; asm("add.rn.f32x2 %0,%1,%2;" : "=l"(d) : "l"(a), "l"(b)); return d;
}
__device__ __forceinline__ float ex2a(float x){
    float y; asm("ex2.approx.f32 %0,%1;" : "=f"(y) : "f"(x)); return y;
}

// ---------------- shared memory layout (float offsets) ----------------
// skv: 2048 positions * 12 floats (k01x,k01y,k01z,v01x,v01y,v01z pairs) = 24576
//      (overlaid by red[16][32][17] = 8704 floats after the attention loop)
// sq : 64 queries * 6 floats  (slots 0-31 = lo queries, 32-63 = hi queries)
// sx : 64 queries * 16 floats (pre-attn residual x for the k3 epilogue)
// sM : 224 floats (M[v][i] = sum_d tok_emb[v,d]*Wh[d,i])
#define SKV_F   0
#define SQ_F    24576
#define SX_F    24960
#define SM_F    25984
#define SMEM_F  26240
#define SMEM_BYTES (SMEM_F*4)

struct Acc { u64 ax, ay, az, den; };

__device__ __forceinline__ void upd(Acc& A, u64 qx, u64 qy, u64 qz,
                                    u64 kx, u64 ky, u64 kz,
                                    u64 vx, u64 vy, u64 vz)
{
    u64 s = fma2(qx, kx, fma2(qy, ky, mul2(qz, kz)));
    float s0, s1; unpack2(s, s0, s1);
    u64 e = pack2(ex2a(s0), ex2a(s1));
    A.den = add2(A.den, e);
    A.ax  = fma2(e, vx, A.ax);
    A.ay  = fma2(e, vy, A.ay);
    A.az  = fma2(e, vz, A.az);
}

// ============================================================================
// Fully fused: embed+LN1+QKV staging (per batch, in smem) -> causal attention
// (16-way split-KV per block, f32x2 over the 2 heads, no-max softmax) ->
// in-block reduction -> Wo+LN2+FFN+LNf+logits epilogue for the block's 64
// queries. Grid = 16 batches x 32 query-pair-groups; block = 512 threads.
// ============================================================================
__global__ void __launch_bounds__(512, 2) fused_kernel(
    const int*   __restrict__ idx,
    const float* __restrict__ tok_emb, const float* __restrict__ pos_enc,
    const float* __restrict__ Wq, const float* __restrict__ Wk,
    const float* __restrict__ Wv, const float* __restrict__ Wo,
    const float* __restrict__ ln1w, const float* __restrict__ ln1b,
    const float* __restrict__ ln2w, const float* __restrict__ ln2b,
    const float* __restrict__ lnfw, const float* __restrict__ lnfb,
    const float* __restrict__ W1,   const float* __restrict__ b1,
    const float* __restrict__ W2,   const float* __restrict__ b2,
    const float* __restrict__ Wh,   float* __restrict__ out)
{
    extern __shared__ float sm[];
    float* skv = sm;
    float* sq  = sm + SQ_F;
    float* sx  = sm + SX_F;
    float* sM  = sm + SM_F;

    int tid  = threadIdx.x;
    int b    = blockIdx.x >> 5;
    int base = (blockIdx.x & 31) << 5;

    // ---- head matrix M = tok_emb @ Wh (14x16), once per block ----
    if (tid < 224){
        int v = tid >> 4, i = tid & 15;
        float s = 0.f;
        #pragma unroll
        for (int d = 0; d < 8; d++)
            s = fmaf(__ldg(tok_emb + v*8 + d), __ldg(Wh + d*16 + i), s);
        sM[tid] = s;
    }

    // ---- staging: embed + LN1 + QKV for the whole batch into smem ----
    const float QS = 0.5773502691896258f * 1.4426950408889634f;  // 1/sqrt(3)*log2e
    #pragma unroll 1
    for (int it = 0; it < 4; it++){
        int t   = tid + it*512;
        int tok = b*T_ + t;
        float x[16];
        int vt = idx[tok];
        #pragma unroll
        for (int i = 0; i < 8; i++) x[i]     = __ldg(tok_emb + vt*8 + i);
        #pragma unroll
        for (int i = 0; i < 8; i++) x[8 + i] = __ldg(pos_enc + t*8 + i);

        float m = 0.f;
        #pragma unroll
        for (int i = 0; i < 16; i++) m += x[i];
        m *= (1.f/16.f);
        float var = 0.f;
        #pragma unroll
        for (int i = 0; i < 16; i++){ float d = x[i] - m; var += d*d; }
        var *= (1.f/16.f);
        float rs = rsqrtf(var + 1e-5f);
        float h[16];
        #pragma unroll
        for (int i = 0; i < 16; i++)
            h[i] = (x[i] - m) * rs * __ldg(ln1w + i) + __ldg(ln1b + i);

        float q[6], k[6], vv[6];
        #pragma unroll
        for (int j = 0; j < 6; j++){
            float aq = 0.f, ak = 0.f, av = 0.f;
            #pragma unroll
            for (int d = 0; d < 8; d++){
                float hp = h[8 + d], ht = h[d];
                aq = fmaf(__ldg(Wq + j*8 + d), hp, aq);
                ak = fmaf(__ldg(Wk + j*8 + d), hp, ak);
                av = fmaf(__ldg(Wv + j*8 + d), ht, av);
            }
            q[j] = aq; k[j] = ak; vv[j] = av;
        }

        float* kd = skv + t*12;
        #pragma unroll
        for (int d = 0; d < 3; d++){
            kd[2*d + 0]     = k[d];
            kd[2*d + 1]     = k[3+d];
            kd[6 + 2*d + 0] = vv[d];
            kd[6 + 2*d + 1] = vv[3+d];
        }

        // q / residual-x only for the block's 64 queries
        int loo = t - base;                 // lo slot if in [0,32)
        int hio = (2047 - base) - t;        // hi slot if in [0,32)
        int slot = -1;
        if ((unsigned)loo < 32u)      slot = loo;
        else if ((unsigned)hio < 32u) slot = 32 + hio;
        if (slot >= 0){
            float* qd = sq + slot*6;
            #pragma unroll
            for (int d = 0; d < 3; d++){
                qd[2*d + 0] = q[d]   * QS;
                qd[2*d + 1] = q[3+d] * QS;
            }
            float* xd = sx + slot*16;
            #pragma unroll
            for (int i = 0; i < 16; i++) xd[i] = x[i];
        }
    }
    __syncthreads();

    // ---- attention: warp w = split (positions w, w+16, ...), lane l = pair ----
    int w   = tid >> 5;
    int l   = tid & 31;
    int qlo = base + l;
    int qhi = 2047 - qlo;

    const u64* qpl = reinterpret_cast<const u64*>(sq + l*6);
    const u64* qph = reinterpret_cast<const u64*>(sq + (32 + l)*6);
    u64 qlx = qpl[0], qly = qpl[1], qlz = qpl[2];
    u64 qhx = qph[0], qhy = qph[1], qhz = qph[2];

    Acc lo; lo.ax = lo.ay = lo.az = lo.den = 0ULL;
    Acc hi; hi.ax = hi.ay = hi.az = hi.den = 0ULL;

    const ulonglong2* kvp = reinterpret_cast<const ulonglong2*>(skv);

    int p = w;
    // Phase A: both queries, unconditional (p <= base <= qlo)
    #pragma unroll 2
    for (; p <= base; p += 16){
        ulonglong2 p0 = kvp[3*p], p1 = kvp[3*p+1], p2 = kvp[3*p+2];
        upd(hi, qhx, qhy, qhz, p0.x, p0.y, p1.x, p1.y, p2.x, p2.y);
        upd(lo, qlx, qly, qlz, p0.x, p0.y, p1.x, p1.y, p2.x, p2.y);
    }
    // Phase B: ragged lo edge (2 iters): hi unconditional, lo predicated
    for (; p < base + 32; p += 16){
        ulonglong2 p0 = kvp[3*p], p1 = kvp[3*p+1], p2 = kvp[3*p+2];
        upd(hi, qhx, qhy, qhz, p0.x, p0.y, p1.x, p1.y, p2.x, p2.y);
        if (p <= qlo)
            upd(lo, qlx, qly, qlz, p0.x, p0.y, p1.x, p1.y, p2.x, p2.y);
    }
    // Phase C: hi only, unconditional (p <= min qhi = 2016 - base)
    int cmax = 2016 - base;
    #pragma unroll 4
    for (; p <= cmax; p += 16){
        ulonglong2 p0 = kvp[3*p], p1 = kvp[3*p+1], p2 = kvp[3*p+2];
        upd(hi, qhx, qhy, qhz, p0.x, p0.y, p1.x, p1.y, p2.x, p2.y);
    }
    // Phase D: ragged hi edge (2 iters), predicated
    int dmax = 2047 - base;
    for (; p <= dmax; p += 16){
        ulonglong2 p0 = kvp[3*p], p1 = kvp[3*p+1], p2 = kvp[3*p+2];
        if (p <= qhi)
            upd(hi, qhx, qhy, qhz, p0.x, p0.y, p1.x, p1.y, p2.x, p2.y);
    }
    __syncthreads();   // all skv reads done; safe to overlay reduction

    // ---- cross-warp reduction (red overlays skv; stride 17 = conflict-free) ----
    float* red = skv;  // [16][32][17]
    {
        float* r = red + (w*32 + l)*17;
        float t0, t1;
        unpack2(lo.den, t0, t1); r[0]  = t0; r[4]  = t1;
        unpack2(lo.ax,  t0, t1); r[1]  = t0; r[5]  = t1;
        unpack2(lo.ay,  t0, t1); r[2]  = t0; r[6]  = t1;
        unpack2(lo.az,  t0, t1); r[3]  = t0; r[7]  = t1;
        unpack2(hi.den, t0, t1); r[8]  = t0; r[12] = t1;
        unpack2(hi.ax,  t0, t1); r[9]  = t0; r[13] = t1;
        unpack2(hi.ay,  t0, t1); r[10] = t0; r[14] = t1;
        unpack2(hi.az,  t0, t1); r[11] = t0; r[15] = t1;
    }
    __syncthreads();

    // ---- epilogue: 64 threads, one per query: reduce + Wo + LN2 + FFN + LNf + logits ----
    if (tid < 64){
        int l2 = tid & 31;
        int hh = tid >> 5;                 // 0 = lo query, 1 = hi query
        float a[8];
        #pragma unroll
        for (int j = 0; j < 8; j++) a[j] = 0.f;
        #pragma unroll
        for (int ww = 0; ww < 16; ww++){
            const float* r = red + (ww*32 + l2)*17 + hh*8;
            #pragma unroll
            for (int j = 0; j < 8; j++) a[j] += r[j];
        }
        float r0 = 1.f / a[0];
        float r1 = 1.f / a[4];
        float o[6];
        o[0] = a[1]*r0; o[1] = a[2]*r0; o[2] = a[3]*r0;   // head0 x,y,z
        o[3] = a[5]*r1; o[4] = a[6]*r1; o[5] = a[7]*r1;   // head1 x,y,z
        // reference order is [h0d0,h0d1,h0d2,h1d0,h1d1,h1d2] — matches o[]

        int q  = hh ? (2047 - (base + l2)) : (base + l2);
        const float* xd = sx + (hh ? (32 + l2) : l2)*16;

        float x[16];
        #pragma unroll
        for (int i = 0; i < 16; i++) x[i] = xd[i];

        // x += attn_out @ Wo^T
        #pragma unroll
        for (int i = 0; i < 16; i++){
            float s = x[i];
            #pragma unroll
            for (int j = 0; j < 6; j++)
                s = fmaf(__ldg(Wo + i*6 + j), o[j], s);
            x[i] = s;
        }

        // LN2
        float m = 0.f;
        #pragma unroll
        for (int i = 0; i < 16; i++) m += x[i];
        m *= (1.f/16.f);
        float var = 0.f;
        #pragma unroll
        for (int i = 0; i < 16; i++){ float d = x[i] - m; var += d*d; }
        var *= (1.f/16.f);
        float rs = rsqrtf(var + 1e-5f);
        float h2[16];
        #pragma unroll
        for (int i = 0; i < 16; i++)
            h2[i] = (x[i] - m) * rs * __ldg(ln2w + i) + __ldg(ln2b + i);

        // FFN with exact gelu
        float g[3];
        #pragma unroll
        for (int j = 0; j < 3; j++){
            float f = __ldg(b1 + j);
            #pragma unroll
            for (int i = 0; i < 16; i++)
                f = fmaf(__ldg(W1 + j*16 + i), h2[i], f);
            g[j] = 0.5f * f * (1.f + erff(f * 0.7071067811865476f));
        }
        #pragma unroll
        for (int i = 0; i < 16; i++){
            float s = x[i] + __ldg(b2 + i);
            s = fmaf(__ldg(W2 + i*3 + 0), g[0], s);
            s = fmaf(__ldg(W2 + i*3 + 1), g[1], s);
            s = fmaf(__ldg(W2 + i*3 + 2), g[2], s);
            x[i] = s;
        }

        // LNf
        m = 0.f;
        #pragma unroll
        for (int i = 0; i < 16; i++) m += x[i];
        m *= (1.f/16.f);
        var = 0.f;
        #pragma unroll
        for (int i = 0; i < 16; i++){ float d = x[i] - m; var += d*d; }
        var *= (1.f/16.f);
        rs = rsqrtf(var + 1e-5f);
        float y[16];
        #pragma unroll
        for (int i = 0; i < 16; i++)
            y[i] = (x[i] - m) * rs * __ldg(lnfw + i) + __ldg(lnfb + i);

        // logits
        float* op = out + ((size_t)b*T_ + q)*14;
        #pragma unroll
        for (int v = 0; v < 14; v++){
            float s = 0.f;
            #pragma unroll
            for (int i = 0; i < 16; i++)
                s = fmaf(y[i], sM[v*16 + i], s);
            op[v] = s;
        }
    }
}

// ============================================================================
extern "C" void kernel_launch(void* const* d_in, const int* in_sizes, int n_in,
                              void* d_out, int out_size)
{
    const int*   idx  = (const int*)  d_in[0];
    const float* tokE = (const float*)d_in[1];
    const float* posE = (const float*)d_in[2];
    const float* Wq   = (const float*)d_in[3];
    const float* Wk   = (const float*)d_in[4];
    const float* Wv   = (const float*)d_in[5];
    const float* Wo   = (const float*)d_in[6];
    const float* ln1w = (const float*)d_in[7];
    const float* ln1b = (const float*)d_in[8];
    const float* ln2w = (const float*)d_in[9];
    const float* ln2b = (const float*)d_in[10];
    const float* lnfw = (const float*)d_in[11];
    const float* lnfb = (const float*)d_in[12];
    const float* W1   = (const float*)d_in[13];
    const float* b1   = (const float*)d_in[14];
    const float* W2   = (const float*)d_in[15];
    const float* b2   = (const float*)d_in[16];
    const float* Wh   = (const float*)d_in[17];
    float* out = (float*)d_out;

    static bool attr_set = false;
    if (!attr_set){
        cudaFuncSetAttribute(fused_kernel,
                             cudaFuncAttributeMaxDynamicSharedMemorySize,
                             SMEM_BYTES);
        attr_set = true;
    }

    fused_kernel<<<16*32, 512, SMEM_BYTES>>>(idx, tokE, posE, Wq, Wk, Wv, Wo,
                                             ln1w, ln1b, ln2w, ln2b, lnfw, lnfb,
                                             W1, b1, W2, b2, Wh, out);
}

// round 5
// speedup vs baseline: 2.9845x; 2.9845x over previous
#include <cuda_runtime.h>
#include <cuda_bf16.h>

#define B_    16
#define T_    2048
#define NTOK  (B_*T_)

// ---------------- scratch (static __device__, no allocations) ----------------
__device__ float g_x[NTOK*16];     // pre-attention residual x
__device__ float g_q[NTOK*6];      // q (head-interleaved pairs), pre-scaled by 1/sqrt(3)*log2(e)
__device__ float g_kv[NTOK*12];    // [kx01,ky01,kz01, vx01,vy01,vz01] head-interleaved

typedef unsigned long long u64;

__device__ __forceinline__ u64 pack2(float lo, float hi){
    u64 r; asm("mov.b64 %0,{%1,%2};" : "=l"(r) : "f"(lo), "f"(hi)); return r;
}
__device__ __forceinline__ void unpack2(u64 v, float& lo, float& hi){
    asm("mov.b64 {%0,%1},%2;" : "=f"(lo), "=f"(hi) : "l"(v));
}
__device__ __forceinline__ u64 fma2(u64 a, u64 b, u64 c){
    u64 d; asm("fma.rn.f32x2 %0,%1,%2,%3;" : "=l"(d) : "l"(a), "l"(b), "l"(c)); return d;
}
__device__ __forceinline__ u64 mul2(u64 a, u64 b){
    u64 d; asm("mul.rn.f32x2 %0,%1,%2;" : "=l"(d) : "l"(a), "l"(b)); return d;
}
__device__ __forceinline__ u64 add2(u64 a, u64 b){
    u64 d; asm("add.rn.f32x2 %0,%1,%2;" : "=l"(d) : "l"(a), "l"(b)); return d;
}
__device__ __forceinline__ float ex2a(float x){
    float y; asm("ex2.approx.f32 %0,%1;" : "=f"(y) : "f"(x)); return y;
}

// ============================================================================
// K1: embed + LN1 + QKV projection (one thread per token)
// ============================================================================
__global__ void __launch_bounds__(128) k1_qkv(
    const int* __restrict__ idx,
    const float* __restrict__ tok_emb,
    const float* __restrict__ pos_enc,
    const float* __restrict__ Wq,
    const float* __restrict__ Wk,
    const float* __restrict__ Wv,
    const float* __restrict__ ln1w,
    const float* __restrict__ ln1b)
{
    int tok = blockIdx.x * 128 + threadIdx.x;
    if (tok >= NTOK) return;
    int t = tok & (T_ - 1);

    float x[16];
    int vt = __ldg(idx + tok);
    #pragma unroll
    for (int i = 0; i < 8; i++) x[i]     = __ldg(tok_emb + vt*8 + i);
    #pragma unroll
    for (int i = 0; i < 8; i++) x[8 + i] = __ldg(pos_enc + t*8 + i);

    float m = 0.f;
    #pragma unroll
    for (int i = 0; i < 16; i++) m += x[i];
    m *= (1.f/16.f);
    float var = 0.f;
    #pragma unroll
    for (int i = 0; i < 16; i++){ float d = x[i] - m; var += d*d; }
    var *= (1.f/16.f);
    float rs = rsqrtf(var + 1e-5f);

    float h[16];
    #pragma unroll
    for (int i = 0; i < 16; i++)
        h[i] = (x[i] - m) * rs * __ldg(ln1w + i) + __ldg(ln1b + i);

    float4* xs = reinterpret_cast<float4*>(g_x + (size_t)tok*16);
    xs[0] = make_float4(x[0],  x[1],  x[2],  x[3]);
    xs[1] = make_float4(x[4],  x[5],  x[6],  x[7]);
    xs[2] = make_float4(x[8],  x[9],  x[10], x[11]);
    xs[3] = make_float4(x[12], x[13], x[14], x[15]);

    float q[6], k[6], vv[6];
    #pragma unroll
    for (int j = 0; j < 6; j++){
        float aq = 0.f, ak = 0.f, av = 0.f;
        #pragma unroll
        for (int d = 0; d < 8; d++){
            float hp = h[8 + d], ht = h[d];
            aq = fmaf(__ldg(Wq + j*8 + d), hp, aq);
            ak = fmaf(__ldg(Wk + j*8 + d), hp, ak);
            av = fmaf(__ldg(Wv + j*8 + d), ht, av);
        }
        q[j] = aq; k[j] = ak; vv[j] = av;
    }

    const float QS = 0.5773502691896258f * 1.4426950408889634f; // 1/sqrt(3)*log2e
    float* gq = g_q  + (size_t)tok*6;
    float* gk = g_kv + (size_t)tok*12;
    #pragma unroll
    for (int d = 0; d < 3; d++){
        gq[2*d + 0]     = q[d]   * QS;
        gq[2*d + 1]     = q[3+d] * QS;
        gk[2*d + 0]     = k[d];
        gk[2*d + 1]     = k[3+d];
        gk[6 + 2*d + 0] = vv[d];
        gk[6 + 2*d + 1] = vv[3+d];
    }
}

// ============================================================================
// K2: causal attention + full epilogue.
// Block = 256 threads = 8 warps. Per block: one batch, 64 query pairs
// (128 queries). KV tile for the whole batch staged into smem (96KB).
// Warp w = sequence split (positions w, w+8, ...); each lane owns 4 queries:
// lo0=base+l, lo1=base+32+l, hi0=2047-lo0, hi1=2047-lo1. One kv LDS feeds
// 4 updates. No-max softmax => split partials are additive. After the smem
// reduction, 128 threads run the Wo/LN2/FFN/LNf/logits epilogue in-place.
// Grid = 16 batches x 16 pair-groups = 256 blocks -> 2 blocks/SM, 1 wave.
// ============================================================================
#define SKV_F    24576                 // 2048 * 12 floats
#define SM_F     24576                 // sM starts after skv
#define SMEM_F   (24576 + 224)
#define SMEM_BYTES (SMEM_F*4)

struct Acc { u64 ax, ay, az, den; };

__device__ __forceinline__ void upd(Acc& A, u64 qx, u64 qy, u64 qz,
                                    u64 kx, u64 ky, u64 kz,
                                    u64 vx, u64 vy, u64 vz)
{
    u64 s = fma2(qx, kx, fma2(qy, ky, mul2(qz, kz)));
    float s0, s1; unpack2(s, s0, s1);
    u64 e = pack2(ex2a(s0), ex2a(s1));
    A.den = add2(A.den, e);
    A.ax  = fma2(e, vx, A.ax);
    A.ay  = fma2(e, vy, A.ay);
    A.az  = fma2(e, vz, A.az);
}

__global__ void __launch_bounds__(256, 2) k2_attn(
    const float* __restrict__ Wo,
    const float* __restrict__ ln2w, const float* __restrict__ ln2b,
    const float* __restrict__ lnfw, const float* __restrict__ lnfb,
    const float* __restrict__ W1,   const float* __restrict__ b1,
    const float* __restrict__ W2,   const float* __restrict__ b2,
    const float* __restrict__ Wh,   const float* __restrict__ tok_emb,
    float* __restrict__ out)
{
    extern __shared__ float smem[];
    float* skv = smem;
    float* sM  = smem + SM_F;

    int tid  = threadIdx.x;
    int b    = blockIdx.x >> 4;
    int base = (blockIdx.x & 15) << 6;       // 0,64,...,960

    // ---- head matrix M = tok_emb @ Wh (14x16) ----
    if (tid < 224){
        int v = tid >> 4, i = tid & 15;
        float s = 0.f;
        #pragma unroll
        for (int d = 0; d < 8; d++)
            s = fmaf(__ldg(tok_emb + v*8 + d), __ldg(Wh + d*16 + i), s);
        sM[tid] = s;
    }

    // ---- stage batch kv tile into smem (coalesced float4) ----
    {
        const float4* src = reinterpret_cast<const float4*>(g_kv + (size_t)b*T_*12);
        float4*       dst = reinterpret_cast<float4*>(skv);
        #pragma unroll
        for (int i = 0; i < 24; i++)
            dst[tid + i*256] = src[tid + i*256];
    }
    __syncthreads();

    // ---- per-thread queries ----
    int w   = tid >> 5;
    int l   = tid & 31;
    int qlo0 = base + l;
    int qlo1 = base + 32 + l;
    int qhi0 = 2047 - qlo0;
    int qhi1 = 2047 - qlo1;

    const u64* qp;
    qp = reinterpret_cast<const u64*>(g_q + ((size_t)b*T_ + qlo0)*6);
    u64 ql0x = qp[0], ql0y = qp[1], ql0z = qp[2];
    qp = reinterpret_cast<const u64*>(g_q + ((size_t)b*T_ + qlo1)*6);
    u64 ql1x = qp[0], ql1y = qp[1], ql1z = qp[2];
    qp = reinterpret_cast<const u64*>(g_q + ((size_t)b*T_ + qhi0)*6);
    u64 qh0x = qp[0], qh0y = qp[1], qh0z = qp[2];
    qp = reinterpret_cast<const u64*>(g_q + ((size_t)b*T_ + qhi1)*6);
    u64 qh1x = qp[0], qh1y = qp[1], qh1z = qp[2];

    Acc lo0; lo0.ax = lo0.ay = lo0.az = lo0.den = 0ULL;
    Acc lo1; lo1.ax = lo1.ay = lo1.az = lo1.den = 0ULL;
    Acc hi0; hi0.ax = hi0.ay = hi0.az = hi0.den = 0ULL;
    Acc hi1; hi1.ax = hi1.ay = hi1.az = hi1.den = 0ULL;

    const ulonglong2* kvp = reinterpret_cast<const ulonglong2*>(skv);

    int p = w;
    // Phase A: p <= base : all four queries, unconditional
    #pragma unroll 2
    for (; p <= base; p += 8){
        ulonglong2 p0 = kvp[3*p], p1 = kvp[3*p+1], p2 = kvp[3*p+2];
        upd(hi0, qh0x, qh0y, qh0z, p0.x, p0.y, p1.x, p1.y, p2.x, p2.y);
        upd(hi1, qh1x, qh1y, qh1z, p0.x, p0.y, p1.x, p1.y, p2.x, p2.y);
        upd(lo0, ql0x, ql0y, ql0z, p0.x, p0.y, p1.x, p1.y, p2.x, p2.y);
        upd(lo1, ql1x, ql1y, ql1z, p0.x, p0.y, p1.x, p1.y, p2.x, p2.y);
    }
    // Phase B: ragged lo edge (8 iters): lo predicated, hi unconditional
    for (; p < base + 64; p += 8){
        ulonglong2 p0 = kvp[3*p], p1 = kvp[3*p+1], p2 = kvp[3*p+2];
        upd(hi0, qh0x, qh0y, qh0z, p0.x, p0.y, p1.x, p1.y, p2.x, p2.y);
        upd(hi1, qh1x, qh1y, qh1z, p0.x, p0.y, p1.x, p1.y, p2.x, p2.y);
        if (p <= qlo0)
            upd(lo0, ql0x, ql0y, ql0z, p0.x, p0.y, p1.x, p1.y, p2.x, p2.y);
        if (p <= qlo1)
            upd(lo1, ql1x, ql1y, ql1z, p0.x, p0.y, p1.x, p1.y, p2.x, p2.y);
    }
    // Phase C: hi only, unconditional (p <= min(qhi1) = 1984 - base)
    int cmax = 1984 - base;
    #pragma unroll 4
    for (; p <= cmax; p += 8){
        ulonglong2 p0 = kvp[3*p], p1 = kvp[3*p+1], p2 = kvp[3*p+2];
        upd(hi0, qh0x, qh0y, qh0z, p0.x, p0.y, p1.x, p1.y, p2.x, p2.y);
        upd(hi1, qh1x, qh1y, qh1z, p0.x, p0.y, p1.x, p1.y, p2.x, p2.y);
    }
    // Phase D: ragged hi edge (8 iters), predicated
    int dmax = 2047 - base;
    for (; p <= dmax; p += 8){
        ulonglong2 p0 = kvp[3*p], p1 = kvp[3*p+1], p2 = kvp[3*p+2];
        if (p <= qhi0)
            upd(hi0, qh0x, qh0y, qh0z, p0.x, p0.y, p1.x, p1.y, p2.x, p2.y);
        if (p <= qhi1)
            upd(hi1, qh1x, qh1y, qh1z, p0.x, p0.y, p1.x, p1.y, p2.x, p2.y);
    }
    __syncthreads();   // all skv reads done; safe to overlay reduction

    // ---- write partials (overlay skv; stride 33 keeps banks clean) ----
    float* red = skv;  // [8][32][33]
    {
        float* r = red + (w*32 + l)*33;
        float t0, t1;
        unpack2(lo0.den, t0, t1); r[0]  = t0; r[4]  = t1;
        unpack2(lo0.ax,  t0, t1); r[1]  = t0; r[5]  = t1;
        unpack2(lo0.ay,  t0, t1); r[2]  = t0; r[6]  = t1;
        unpack2(lo0.az,  t0, t1); r[3]  = t0; r[7]  = t1;
        unpack2(lo1.den, t0, t1); r[8]  = t0; r[12] = t1;
        unpack2(lo1.ax,  t0, t1); r[9]  = t0; r[13] = t1;
        unpack2(lo1.ay,  t0, t1); r[10] = t0; r[14] = t1;
        unpack2(lo1.az,  t0, t1); r[11] = t0; r[15] = t1;
        unpack2(hi0.den, t0, t1); r[16] = t0; r[20] = t1;
        unpack2(hi0.ax,  t0, t1); r[17] = t0; r[21] = t1;
        unpack2(hi0.ay,  t0, t1); r[18] = t0; r[22] = t1;
        unpack2(hi0.az,  t0, t1); r[19] = t0; r[23] = t1;
        unpack2(hi1.den, t0, t1); r[24] = t0; r[28] = t1;
        unpack2(hi1.ax,  t0, t1); r[25] = t0; r[29] = t1;
        unpack2(hi1.ay,  t0, t1); r[26] = t0; r[30] = t1;
        unpack2(hi1.az,  t0, t1); r[27] = t0; r[31] = t1;
    }
    __syncthreads();

    // ---- epilogue: 128 threads, one query each ----
    if (tid < 128){
        int Qi = tid >> 5;                 // 0=lo0, 1=lo1, 2=hi0, 3=hi1
        int l2 = tid & 31;
        float a[8];
        #pragma unroll
        for (int j = 0; j < 8; j++) a[j] = 0.f;
        #pragma unroll
        for (int ww = 0; ww < 8; ww++){
            const float* r = red + (ww*32 + l2)*33 + Qi*8;
            #pragma unroll
            for (int j = 0; j < 8; j++) a[j] += r[j];
        }
        int q;
        if      (Qi == 0) q = base + l2;
        else if (Qi == 1) q = base + 32 + l2;
        else if (Qi == 2) q = 2047 - (base + l2);
        else              q = 2047 - (base + 32 + l2);

        float r0 = 1.f / a[0];
        float r1 = 1.f / a[4];
        float o[6];
        o[0] = a[1]*r0; o[1] = a[2]*r0; o[2] = a[3]*r0;   // head0 d0,d1,d2
        o[3] = a[5]*r1; o[4] = a[6]*r1; o[5] = a[7]*r1;   // head1 d0,d1,d2

        float x[16];
        const float4* xs = reinterpret_cast<const float4*>(g_x + ((size_t)b*T_ + q)*16);
        float4 a0 = xs[0], a1 = xs[1], a2 = xs[2], a3 = xs[3];
        x[0]=a0.x; x[1]=a0.y; x[2]=a0.z; x[3]=a0.w;
        x[4]=a1.x; x[5]=a1.y; x[6]=a1.z; x[7]=a1.w;
        x[8]=a2.x; x[9]=a2.y; x[10]=a2.z; x[11]=a2.w;
        x[12]=a3.x; x[13]=a3.y; x[14]=a3.z; x[15]=a3.w;

        // x += attn_out @ Wo^T
        #pragma unroll
        for (int i = 0; i < 16; i++){
            float s = x[i];
            #pragma unroll
            for (int j = 0; j < 6; j++)
                s = fmaf(__ldg(Wo + i*6 + j), o[j], s);
            x[i] = s;
        }

        // LN2
        float m = 0.f;
        #pragma unroll
        for (int i = 0; i < 16; i++) m += x[i];
        m *= (1.f/16.f);
        float var = 0.f;
        #pragma unroll
        for (int i = 0; i < 16; i++){ float d = x[i] - m; var += d*d; }
        var *= (1.f/16.f);
        float rs = rsqrtf(var + 1e-5f);
        float h2[16];
        #pragma unroll
        for (int i = 0; i < 16; i++)
            h2[i] = (x[i] - m) * rs * __ldg(ln2w + i) + __ldg(ln2b + i);

        // FFN with exact gelu
        float g[3];
        #pragma unroll
        for (int j = 0; j < 3; j++){
            float f = __ldg(b1 + j);
            #pragma unroll
            for (int i = 0; i < 16; i++)
                f = fmaf(__ldg(W1 + j*16 + i), h2[i], f);
            g[j] = 0.5f * f * (1.f + erff(f * 0.7071067811865476f));
        }
        #pragma unroll
        for (int i = 0; i < 16; i++){
            float s = x[i] + __ldg(b2 + i);
            s = fmaf(__ldg(W2 + i*3 + 0), g[0], s);
            s = fmaf(__ldg(W2 + i*3 + 1), g[1], s);
            s = fmaf(__ldg(W2 + i*3 + 2), g[2], s);
            x[i] = s;
        }

        // LNf
        m = 0.f;
        #pragma unroll
        for (int i = 0; i < 16; i++) m += x[i];
        m *= (1.f/16.f);
        var = 0.f;
        #pragma unroll
        for (int i = 0; i < 16; i++){ float d = x[i] - m; var += d*d; }
        var *= (1.f/16.f);
        rs = rsqrtf(var + 1e-5f);
        float y[16];
        #pragma unroll
        for (int i = 0; i < 16; i++)
            y[i] = (x[i] - m) * rs * __ldg(lnfw + i) + __ldg(lnfb + i);

        // logits
        float* op = out + ((size_t)b*T_ + q)*14;
        #pragma unroll
        for (int v = 0; v < 14; v++){
            float s = 0.f;
            #pragma unroll
            for (int i = 0; i < 16; i++)
                s = fmaf(y[i], sM[v*16 + i], s);
            op[v] = s;
        }
    }
}

// ============================================================================
extern "C" void kernel_launch(void* const* d_in, const int* in_sizes, int n_in,
                              void* d_out, int out_size)
{
    const int*   idx  = (const int*)  d_in[0];
    const float* tokE = (const float*)d_in[1];
    const float* posE = (const float*)d_in[2];
    const float* Wq   = (const float*)d_in[3];
    const float* Wk   = (const float*)d_in[4];
    const float* Wv   = (const float*)d_in[5];
    const float* Wo   = (const float*)d_in[6];
    const float* ln1w = (const float*)d_in[7];
    const float* ln1b = (const float*)d_in[8];
    const float* ln2w = (const float*)d_in[9];
    const float* ln2b = (const float*)d_in[10];
    const float* lnfw = (const float*)d_in[11];
    const float* lnfb = (const float*)d_in[12];
    const float* W1   = (const float*)d_in[13];
    const float* b1   = (const float*)d_in[14];
    const float* W2   = (const float*)d_in[15];
    const float* b2   = (const float*)d_in[16];
    const float* Wh   = (const float*)d_in[17];
    float* out = (float*)d_out;

    static bool attr_set = false;
    if (!attr_set){
        cudaFuncSetAttribute(k2_attn,
                             cudaFuncAttributeMaxDynamicSharedMemorySize,
                             SMEM_BYTES);
        attr_set = true;
    }

    k1_qkv<<<NTOK/128, 128>>>(idx, tokE, posE, Wq, Wk, Wv, ln1w, ln1b);
    k2_attn<<<256, 256, SMEM_BYTES>>>(Wo, ln2w, ln2b, lnfw, lnfb,
                                      W1, b1, W2, b2, Wh, tokE, out);
}

// round 6
// speedup vs baseline: 3.6361x; 1.2183x over previous
#include <cuda_runtime.h>
#include <cuda_fp16.h>

#define B_    16
#define T_    2048
#define NTOK  (B_*T_)

// ---------------- scratch (static __device__, no allocations) ----------------
__device__ float g_x[NTOK*16];     // pre-attention residual x (fp32 — residual path stays exact)
__device__ uint4 g_q4[NTOK];       // qx,qy,qz as half2 (head0 lo, head1 hi), QS-folded; .w pad
__device__ uint4 g_kvA[NTOK];      // kx,ky,kz,vx as half2
__device__ uint2 g_kvB[NTOK];      // vy,vz as half2

typedef unsigned int u32;

__device__ __forceinline__ u32 hfma2(u32 a, u32 b, u32 c){
    u32 d; asm("fma.rn.f16x2 %0,%1,%2,%3;" : "=r"(d) : "r"(a), "r"(b), "r"(c)); return d;
}
__device__ __forceinline__ u32 hmul2(u32 a, u32 b){
    u32 d; asm("mul.rn.f16x2 %0,%1,%2;" : "=r"(d) : "r"(a), "r"(b)); return d;
}
__device__ __forceinline__ u32 hadd2(u32 a, u32 b){
    u32 d; asm("add.rn.f16x2 %0,%1,%2;" : "=r"(d) : "r"(a), "r"(b)); return d;
}
__device__ __forceinline__ u32 hex2(u32 x){
    u32 y; asm("ex2.approx.f16x2 %0,%1;" : "=r"(y) : "r"(x)); return y;
}
__device__ __forceinline__ u32 packh2(float lo, float hi){
    __half2 h = __floats2half2_rn(lo, hi);
    return *reinterpret_cast<u32*>(&h);
}

// ============================================================================
// K1: embed + LN1 + QKV projection (one thread per token)
// ============================================================================
__global__ void __launch_bounds__(128) k1_qkv(
    const int* __restrict__ idx,
    const float* __restrict__ tok_emb,
    const float* __restrict__ pos_enc,
    const float* __restrict__ Wq,
    const float* __restrict__ Wk,
    const float* __restrict__ Wv,
    const float* __restrict__ ln1w,
    const float* __restrict__ ln1b)
{
    int tok = blockIdx.x * 128 + threadIdx.x;
    if (tok >= NTOK) return;
    int t = tok & (T_ - 1);

    float x[16];
    int vt = __ldg(idx + tok);
    #pragma unroll
    for (int i = 0; i < 8; i++) x[i]     = __ldg(tok_emb + vt*8 + i);
    #pragma unroll
    for (int i = 0; i < 8; i++) x[8 + i] = __ldg(pos_enc + t*8 + i);

    float m = 0.f;
    #pragma unroll
    for (int i = 0; i < 16; i++) m += x[i];
    m *= (1.f/16.f);
    float var = 0.f;
    #pragma unroll
    for (int i = 0; i < 16; i++){ float d = x[i] - m; var += d*d; }
    var *= (1.f/16.f);
    float rs = rsqrtf(var + 1e-5f);

    float h[16];
    #pragma unroll
    for (int i = 0; i < 16; i++)
        h[i] = (x[i] - m) * rs * __ldg(ln1w + i) + __ldg(ln1b + i);

    float4* xs = reinterpret_cast<float4*>(g_x + (size_t)tok*16);
    xs[0] = make_float4(x[0],  x[1],  x[2],  x[3]);
    xs[1] = make_float4(x[4],  x[5],  x[6],  x[7]);
    xs[2] = make_float4(x[8],  x[9],  x[10], x[11]);
    xs[3] = make_float4(x[12], x[13], x[14], x[15]);

    float q[6], k[6], vv[6];
    #pragma unroll
    for (int j = 0; j < 6; j++){
        float aq = 0.f, ak = 0.f, av = 0.f;
        #pragma unroll
        for (int d = 0; d < 8; d++){
            float hp = h[8 + d], ht = h[d];
            aq = fmaf(__ldg(Wq + j*8 + d), hp, aq);
            ak = fmaf(__ldg(Wk + j*8 + d), hp, ak);
            av = fmaf(__ldg(Wv + j*8 + d), ht, av);
        }
        q[j] = aq; k[j] = ak; vv[j] = av;
    }

    const float QS = 0.5773502691896258f * 1.4426950408889634f; // 1/sqrt(3)*log2e
    uint4 qo;
    qo.x = packh2(q[0]*QS, q[3]*QS);
    qo.y = packh2(q[1]*QS, q[4]*QS);
    qo.z = packh2(q[2]*QS, q[5]*QS);
    qo.w = 0;
    g_q4[tok] = qo;

    uint4 A;
    A.x = packh2(k[0],  k[3]);
    A.y = packh2(k[1],  k[4]);
    A.z = packh2(k[2],  k[5]);
    A.w = packh2(vv[0], vv[3]);
    g_kvA[tok] = A;
    uint2 Bv;
    Bv.x = packh2(vv[1], vv[4]);
    Bv.y = packh2(vv[2], vv[5]);
    g_kvB[tok] = Bv;
}

// ============================================================================
// K2: causal attention + full epilogue, fp16 datapath.
// Block = 256 thr = 8 warps; one batch, 32 query pairs (qlo=base+l, qhi=2047-qlo).
// Warp w = sequence split (positions w, w+8, ...). KV tile (48KB fp16) in smem.
// Score: 3x HFMA2 (both heads packed); exp: 1x ex2.approx.f16x2; accumulate in
// f16x2 chunk accumulators, promoted to fp32 masters every 8 iterations (64
// positions). No-max softmax -> split partials additive. Grid = 16 x 32 = 512
// blocks, 4 blocks/SM.
// ============================================================================
#define SA_BYTES  32768                       // 2048 * uint4
#define SB_BYTES  16384                       // 2048 * uint2
#define SM_OFF    (SA_BYTES + SB_BYTES)
#define SMEM_BYTES (SM_OFF + 224*4)

__device__ __forceinline__ void updh(u32* a, u32 qx, u32 qy, u32 qz,
                                     u32 kx, u32 ky, u32 kz,
                                     u32 vx, u32 vy, u32 vz)
{
    u32 s = hfma2(qx, kx, hfma2(qy, ky, hmul2(qz, kz)));
    u32 e = hex2(s);
    a[0] = hadd2(a[0], e);
    a[1] = hfma2(e, vx, a[1]);
    a[2] = hfma2(e, vy, a[2]);
    a[3] = hfma2(e, vz, a[3]);
}

__device__ __forceinline__ void promote(float* m, u32* c)
{
    #pragma unroll
    for (int k = 0; k < 4; k++){
        float2 t = __half22float2(*reinterpret_cast<__half2*>(&c[k]));
        m[2*k]   += t.x;
        m[2*k+1] += t.y;
        c[k] = 0u;
    }
}

__global__ void __launch_bounds__(256, 4) k2_attn(
    const float* __restrict__ Wo,
    const float* __restrict__ ln2w, const float* __restrict__ ln2b,
    const float* __restrict__ lnfw, const float* __restrict__ lnfb,
    const float* __restrict__ W1,   const float* __restrict__ b1,
    const float* __restrict__ W2,   const float* __restrict__ b2,
    const float* __restrict__ Wh,   const float* __restrict__ tok_emb,
    float* __restrict__ out)
{
    extern __shared__ char smem[];
    uint4* sA = reinterpret_cast<uint4*>(smem);
    uint2* sB = reinterpret_cast<uint2*>(smem + SA_BYTES);
    float* sM = reinterpret_cast<float*>(smem + SM_OFF);
    float* red = reinterpret_cast<float*>(smem);   // overlays sA after the loop

    int tid  = threadIdx.x;
    int w    = tid >> 5;
    int l    = tid & 31;
    int b    = blockIdx.x >> 5;
    int base = (blockIdx.x & 31) << 5;             // 0,32,...,992

    // ---- head matrix M = tok_emb @ Wh (14x16) ----
    if (tid < 224){
        int v = tid >> 4, i = tid & 15;
        float s = 0.f;
        #pragma unroll
        for (int d = 0; d < 8; d++)
            s = fmaf(__ldg(tok_emb + v*8 + d), __ldg(Wh + d*16 + i), s);
        sM[tid] = s;
    }

    // ---- stage fp16 kv tile (coalesced) ----
    {
        const uint4* srcA = g_kvA + (size_t)b*T_;
        #pragma unroll
        for (int i = 0; i < 8; i++) sA[tid + i*256] = srcA[tid + i*256];
        const uint2* srcB = g_kvB + (size_t)b*T_;
        #pragma unroll
        for (int i = 0; i < 8; i++) sB[tid + i*256] = srcB[tid + i*256];
    }
    __syncthreads();

    int qlo = base + l;
    int qhi = 2047 - qlo;

    uint4 qa = g_q4[(size_t)b*T_ + qlo];
    uint4 qb = g_q4[(size_t)b*T_ + qhi];
    u32 qlx = qa.x, qly = qa.y, qlz = qa.z;
    u32 qhx = qb.x, qhy = qb.y, qhz = qb.z;

    u32 cl[4] = {0,0,0,0};                 // lo chunk accum (half2: den,ax,ay,az)
    u32 ch[4] = {0,0,0,0};                 // hi chunk accum
    float ml[8], mh[8];                    // fp32 masters (den0,den1,ax0,ax1,ay0,ay1,az0,az1)
    #pragma unroll
    for (int i = 0; i < 8; i++){ ml[i] = 0.f; mh[i] = 0.f; }

    int j = base >> 6;                     // lo-edge chunk
    int h = 31 - j;                        // hi-edge chunk
    // chunk c covers positions [64c, 64c+64), 8 iterations of stride 8 from w.

    int c = 0;
    // chunks 0..j-1: both queries, unconditional
    for (; c < j; c++){
        int p = c*64 + w;
        #pragma unroll 4
        for (int i = 0; i < 8; i++, p += 8){
            uint4 A = sA[p]; uint2 Bv = sB[p];
            updh(ch, qhx,qhy,qhz, A.x,A.y,A.z, A.w,Bv.x,Bv.y);
            updh(cl, qlx,qly,qlz, A.x,A.y,A.z, A.w,Bv.x,Bv.y);
        }
        promote(mh, ch); promote(ml, cl);
    }
    // chunk j: hi unconditional, lo predicated
    {
        int p = c*64 + w;
        #pragma unroll 4
        for (int i = 0; i < 8; i++, p += 8){
            uint4 A = sA[p]; uint2 Bv = sB[p];
            updh(ch, qhx,qhy,qhz, A.x,A.y,A.z, A.w,Bv.x,Bv.y);
            if (p <= qlo)
                updh(cl, qlx,qly,qlz, A.x,A.y,A.z, A.w,Bv.x,Bv.y);
        }
        promote(mh, ch); promote(ml, cl);
        c++;
    }
    // chunks j+1..h-1: hi only, unconditional
    for (; c < h; c++){
        int p = c*64 + w;
        #pragma unroll 4
        for (int i = 0; i < 8; i++, p += 8){
            uint4 A = sA[p]; uint2 Bv = sB[p];
            updh(ch, qhx,qhy,qhz, A.x,A.y,A.z, A.w,Bv.x,Bv.y);
        }
        promote(mh, ch);
    }
    // chunk h: hi predicated
    {
        int p = c*64 + w;
        #pragma unroll 4
        for (int i = 0; i < 8; i++, p += 8){
            uint4 A = sA[p]; uint2 Bv = sB[p];
            if (p <= qhi)
                updh(ch, qhx,qhy,qhz, A.x,A.y,A.z, A.w,Bv.x,Bv.y);
        }
        promote(mh, ch);
    }
    __syncthreads();   // all sA reads done; safe to overlay reduction

    // ---- write partials (stride 17 = conflict-free) ----
    {
        float* r = red + (w*32 + l)*17;
        #pragma unroll
        for (int i = 0; i < 8; i++) r[i]     = ml[i];
        #pragma unroll
        for (int i = 0; i < 8; i++) r[8 + i] = mh[i];
    }
    __syncthreads();

    // ---- epilogue: 64 threads, one query each ----
    if (tid < 64){
        int Qi = tid >> 5;                 // 0 = lo query, 1 = hi query
        int l2 = tid & 31;
        float a[8];
        #pragma unroll
        for (int i = 0; i < 8; i++) a[i] = 0.f;
        #pragma unroll
        for (int ww = 0; ww < 8; ww++){
            const float* r = red + (ww*32 + l2)*17 + Qi*8;
            #pragma unroll
            for (int i = 0; i < 8; i++) a[i] += r[i];
        }
        int q = Qi ? (2047 - (base + l2)) : (base + l2);

        // a = [den0,den1,ax0,ax1,ay0,ay1,az0,az1]
        float r0 = 1.f / a[0];
        float r1 = 1.f / a[1];
        float o[6];
        o[0] = a[2]*r0; o[1] = a[4]*r0; o[2] = a[6]*r0;   // head0 d0,d1,d2
        o[3] = a[3]*r1; o[4] = a[5]*r1; o[5] = a[7]*r1;   // head1 d0,d1,d2

        float x[16];
        const float4* xs = reinterpret_cast<const float4*>(g_x + ((size_t)b*T_ + q)*16);
        float4 a0 = xs[0], a1 = xs[1], a2 = xs[2], a3 = xs[3];
        x[0]=a0.x; x[1]=a0.y; x[2]=a0.z; x[3]=a0.w;
        x[4]=a1.x; x[5]=a1.y; x[6]=a1.z; x[7]=a1.w;
        x[8]=a2.x; x[9]=a2.y; x[10]=a2.z; x[11]=a2.w;
        x[12]=a3.x; x[13]=a3.y; x[14]=a3.z; x[15]=a3.w;

        // x += attn_out @ Wo^T
        #pragma unroll
        for (int i = 0; i < 16; i++){
            float s = x[i];
            #pragma unroll
            for (int jj = 0; jj < 6; jj++)
                s = fmaf(__ldg(Wo + i*6 + jj), o[jj], s);
            x[i] = s;
        }

        // LN2
        float m = 0.f;
        #pragma unroll
        for (int i = 0; i < 16; i++) m += x[i];
        m *= (1.f/16.f);
        float var = 0.f;
        #pragma unroll
        for (int i = 0; i < 16; i++){ float d = x[i] - m; var += d*d; }
        var *= (1.f/16.f);
        float rs = rsqrtf(var + 1e-5f);
        float h2[16];
        #pragma unroll
        for (int i = 0; i < 16; i++)
            h2[i] = (x[i] - m) * rs * __ldg(ln2w + i) + __ldg(ln2b + i);

        // FFN with exact gelu
        float g[3];
        #pragma unroll
        for (int jj = 0; jj < 3; jj++){
            float f = __ldg(b1 + jj);
            #pragma unroll
            for (int i = 0; i < 16; i++)
                f = fmaf(__ldg(W1 + jj*16 + i), h2[i], f);
            g[jj] = 0.5f * f * (1.f + erff(f * 0.7071067811865476f));
        }
        #pragma unroll
        for (int i = 0; i < 16; i++){
            float s = x[i] + __ldg(b2 + i);
            s = fmaf(__ldg(W2 + i*3 + 0), g[0], s);
            s = fmaf(__ldg(W2 + i*3 + 1), g[1], s);
            s = fmaf(__ldg(W2 + i*3 + 2), g[2], s);
            x[i] = s;
        }

        // LNf
        m = 0.f;
        #pragma unroll
        for (int i = 0; i < 16; i++) m += x[i];
        m *= (1.f/16.f);
        var = 0.f;
        #pragma unroll
        for (int i = 0; i < 16; i++){ float d = x[i] - m; var += d*d; }
        var *= (1.f/16.f);
        rs = rsqrtf(var + 1e-5f);
        float y[16];
        #pragma unroll
        for (int i = 0; i < 16; i++)
            y[i] = (x[i] - m) * rs * __ldg(lnfw + i) + __ldg(lnfb + i);

        // logits
        float* op = out + ((size_t)b*T_ + q)*14;
        #pragma unroll
        for (int v = 0; v < 14; v++){
            float s = 0.f;
            #pragma unroll
            for (int i = 0; i < 16; i++)
                s = fmaf(y[i], sM[v*16 + i], s);
            op[v] = s;
        }
    }
}

// ============================================================================
extern "C" void kernel_launch(void* const* d_in, const int* in_sizes, int n_in,
                              void* d_out, int out_size)
{
    const int*   idx  = (const int*)  d_in[0];
    const float* tokE = (const float*)d_in[1];
    const float* posE = (const float*)d_in[2];
    const float* Wq   = (const float*)d_in[3];
    const float* Wk   = (const float*)d_in[4];
    const float* Wv   = (const float*)d_in[5];
    const float* Wo   = (const float*)d_in[6];
    const float* ln1w = (const float*)d_in[7];
    const float* ln1b = (const float*)d_in[8];
    const float* ln2w = (const float*)d_in[9];
    const float* ln2b = (const float*)d_in[10];
    const float* lnfw = (const float*)d_in[11];
    const float* lnfb = (const float*)d_in[12];
    const float* W1   = (const float*)d_in[13];
    const float* b1   = (const float*)d_in[14];
    const float* W2   = (const float*)d_in[15];
    const float* b2   = (const float*)d_in[16];
    const float* Wh   = (const float*)d_in[17];
    float* out = (float*)d_out;

    static bool attr_set = false;
    if (!attr_set){
        cudaFuncSetAttribute(k2_attn,
                             cudaFuncAttributeMaxDynamicSharedMemorySize,
                             SMEM_BYTES);
        attr_set = true;
    }

    k1_qkv<<<NTOK/128, 128>>>(idx, tokE, posE, Wq, Wk, Wv, ln1w, ln1b);
    k2_attn<<<16*32, 256, SMEM_BYTES>>>(Wo, ln2w, ln2b, lnfw, lnfb,
                                        W1, b1, W2, b2, Wh, tokE, out);
}